// round 14
// baseline (speedup 1.0000x reference)
#include <cuda_runtime.h>
#include <cuda_bf16.h>
#include <cstdint>

#define NROWS 16384
#define FIN 64
#define FOUT 64
#define NP 80             // g_B row: 0..63 = feat@W2^T, 64 = ones, 65..79 = 0
#define NC 72             // stored C cols
#define MT 128            // M rows per CTA
#define KC 64             // K per chunk
#define KHALF (NROWS / 2)
#define NCHUNK (KHALF / KC)     // 128
#define SA 72             // A smem stride (bf16): conflict-free LDSM
#define SB 88             // B smem stride (bf16): conflict-free LDSM
#define ASTG 2
#define BSTG 3
#define A_STG_BYTES (MT * SA * 2)     // 18432
#define B_STG_BYTES (KC * SB * 2)     // 11264
#define GEMM_SMEM (ASTG * A_STG_BYTES + BSTG * B_STG_BYTES)   // 70656
#define PREPB_SMEM ((64 * 65 + 64 * 64) * 4)                  // 33024
#define EPI_SMEM ((64 * 64 + 32 * 65 + 32) * 4)               // 24832
#define NBLK (NROWS / MT)       // 128 row blocks

__device__ __align__(256) __nv_bfloat16 g_B[NROWS * NP];
__device__ __align__(256) float g_Cp[2][NROWS * NC];

__device__ __forceinline__ uint32_t smem_u32(const void* p) {
  uint32_t a;
  asm("{ .reg .u64 t; cvta.to.shared.u64 t, %1; cvt.u32.u64 %0, t; }" : "=r"(a) : "l"(p));
  return a;
}
__device__ __forceinline__ void cp16(uint32_t dst, const void* src) {
  asm volatile("cp.async.cg.shared.global [%0], [%1], 16;" :: "r"(dst), "l"(src));
}
#define CP_COMMIT() asm volatile("cp.async.commit_group;" ::: "memory")
#define CP_WAIT1()  asm volatile("cp.async.wait_group 1;" ::: "memory")
__device__ __forceinline__ void ldsm_x4(uint32_t* r, uint32_t a) {
  asm volatile("ldmatrix.sync.aligned.m8n8.x4.shared.b16 {%0,%1,%2,%3}, [%4];"
               : "=r"(r[0]), "=r"(r[1]), "=r"(r[2]), "=r"(r[3]) : "r"(a));
}
__device__ __forceinline__ void ldsm_x4t(uint32_t* r, uint32_t a) {
  asm volatile("ldmatrix.sync.aligned.m8n8.x4.trans.shared.b16 {%0,%1,%2,%3}, [%4];"
               : "=r"(r[0]), "=r"(r[1]), "=r"(r[2]), "=r"(r[3]) : "r"(a));
}
__device__ __forceinline__ void ldsm_x2t(uint32_t* r, uint32_t a) {
  asm volatile("ldmatrix.sync.aligned.m8n8.x2.trans.shared.b16 {%0,%1}, [%2];"
               : "=r"(r[0]), "=r"(r[1]) : "r"(a));
}
__device__ __forceinline__ void mma_bf16(float* c, const uint32_t* a, uint32_t b0, uint32_t b1) {
  asm volatile(
      "mma.sync.aligned.m16n8k16.row.col.f32.bf16.bf16.f32 "
      "{%0,%1,%2,%3}, {%4,%5,%6,%7}, {%8,%9}, {%0,%1,%2,%3};\n"
      : "+f"(c[0]), "+f"(c[1]), "+f"(c[2]), "+f"(c[3])
      : "r"(a[0]), "r"(a[1]), "r"(a[2]), "r"(a[3]), "r"(b0), "r"(b1));
}

// ---------------------------------------------------------------------------
// prep_B: g_B[k][0..63] = (feat@W2^T) bf16; col 64 = 1; cols 65..79 = 0.
// 256 thr, q = warp>>1 in 0..3 -> 16 cols each; Wt2 j-major, warp-broadcast.
// ---------------------------------------------------------------------------
__global__ __launch_bounds__(256, 2) void prepB_kernel(const float* __restrict__ feat,
                                                       const float* __restrict__ W) {
  extern __shared__ float sm[];
  float* Fs = sm;             // [64][65]
  float* Wt = sm + 64 * 65;   // [64][64]: Wt[j][o] = W2[o][j] = W[o*128 + 64 + j]
  const int tid = threadIdx.x;
  const int k0 = blockIdx.x * 64;

  for (int idx = tid; idx < 64 * 64; idx += 256) {
    int r = idx >> 6, j = idx & 63;
    Fs[r * 65 + j] = feat[(size_t)(k0 + r) * 64 + j];
  }
  for (int idx = tid; idx < 64 * 64; idx += 256) {
    int o = idx >> 6, j = idx & 63;
    Wt[j * 64 + o] = W[o * 128 + 64 + j];
  }
  __syncthreads();

  const int r = tid & 63;
  const int q = tid >> 6;     // 0..3, warp-uniform
  float acc[16];
#pragma unroll
  for (int o = 0; o < 16; ++o) acc[o] = 0.0f;

#pragma unroll 4
  for (int j = 0; j < 64; ++j) {
    const float f = Fs[r * 65 + j];
    const float4* w4 = (const float4*)(Wt + j * 64 + q * 16);  // warp-broadcast
#pragma unroll
    for (int v = 0; v < 4; ++v) {
      const float4 w = w4[v];
      acc[4 * v + 0] += f * w.x;
      acc[4 * v + 1] += f * w.y;
      acc[4 * v + 2] += f * w.z;
      acc[4 * v + 3] += f * w.w;
    }
  }

  __nv_bfloat162* dst = (__nv_bfloat162*)(g_B + (size_t)(k0 + r) * NP + q * 16);
#pragma unroll
  for (int v = 0; v < 8; ++v)
    dst[v] = __floats2bfloat162_rn(acc[2 * v], acc[2 * v + 1]);

  for (int idx = tid; idx < 64 * 16; idx += 256) {
    int rr = idx >> 4, c = 64 + (idx & 15);
    g_B[(size_t)(k0 + rr) * NP + c] = __float2bfloat16((c == 64) ? 1.0f : 0.0f);
  }
}

// ---------------------------------------------------------------------------
// gemm (r8/r12 structure, exact): Cp[kh][rowBlk] = adj(rows, k-half) @ g_B
// ---------------------------------------------------------------------------
__global__ __launch_bounds__(256, 2) void gemm_kernel(const float* __restrict__ adj) {
  extern __shared__ __align__(128) char smem[];
  __nv_bfloat16* As = (__nv_bfloat16*)smem;
  __nv_bfloat16* Bs = (__nv_bfloat16*)(smem + ASTG * A_STG_BYTES);

  const int tid = threadIdx.x;
  const int warp = tid >> 5;
  const int lane = tid & 31;
  const int wm = warp >> 1;
  const int wn = warp & 1;
  const int rowBlk = blockIdx.x >> 1;
  const int kh = blockIdx.x & 1;
  const int i0 = rowBlk * MT;
  const size_t kbase0 = (size_t)kh * KHALF;

  const int r0 = tid >> 4;
  const int c4 = tid & 15;
  const float* apc = adj + (size_t)(i0 + r0) * NROWS + kbase0 + c4 * 4;
  const uint32_t a_base = smem_u32(As);
  const uint32_t aSt0 = a_base + (uint32_t)(r0 * SA + c4 * 4) * 2;

  const int br0 = tid / 10, bc0 = tid % 10;
  const int br1 = (tid + 256) / 10, bc1 = (tid + 256) % 10;
  const int br2 = (tid + 512) / 10, bc2 = (tid + 512) % 10;
  const bool bok2 = tid < 128;
  const uint32_t bs_base = smem_u32(Bs);
  const __nv_bfloat16* bsrc0 = g_B + (kbase0 + br0) * NP + bc0 * 8;
  const __nv_bfloat16* bsrc1 = g_B + (kbase0 + br1) * NP + bc1 * 8;
  const __nv_bfloat16* bsrc2 = g_B + (kbase0 + br2) * NP + bc2 * 8;
  const uint32_t bd0 = (uint32_t)(br0 * SB * 2 + bc0 * 16);
  const uint32_t bd1 = (uint32_t)(br1 * SB * 2 + bc1 * 16);
  const uint32_t bd2 = (uint32_t)(br2 * SB * 2 + bc2 * 16);

  const uint32_t aAddr = a_base +
      (uint32_t)((wm * 32 + (lane & 15)) * SA + (lane >> 4) * 8) * 2;
  const int bRow = lane & 15;
  const int nOff = (lane >> 4) * 8;
  const uint32_t bAddrP0 = bs_base + (uint32_t)(bRow * SB + wn * 40 + nOff) * 2;
  const uint32_t bAddrP1 = bAddrP0 + 16 * 2;
  const uint32_t bAddr4 = bs_base + (uint32_t)(bRow * SB + 32 + nOff) * 2;

  float4 rA[8];
  auto loadA = [&]() {
#pragma unroll
    for (int j = 0; j < 8; ++j) {
      asm volatile("ld.global.nc.L2::128B.v4.f32 {%0,%1,%2,%3}, [%4];"
                   : "=f"(rA[j].x), "=f"(rA[j].y), "=f"(rA[j].z), "=f"(rA[j].w)
                   : "l"(apc + (size_t)j * 16 * NROWS));
    }
    apc += KC;
  };
  auto stsA = [&](int stg) {
    const uint32_t base = aSt0 + (uint32_t)(stg * A_STG_BYTES);
#pragma unroll
    for (int j = 0; j < 8; ++j) {
      __nv_bfloat162 lo = __floats2bfloat162_rn(rA[j].x, rA[j].y);
      __nv_bfloat162 hi = __floats2bfloat162_rn(rA[j].z, rA[j].w);
      asm volatile("st.shared.v2.b32 [%0], {%1,%2};"
                   :: "r"(base + (uint32_t)(j * 16 * SA * 2)),
                      "r"(*(uint32_t*)&lo), "r"(*(uint32_t*)&hi)
                   : "memory");
    }
  };
  auto issueB = [&](int ch, int stg) {
    const uint32_t dst = bs_base + (uint32_t)(stg * B_STG_BYTES);
    const size_t off = (size_t)ch * KC * NP;
    cp16(dst + bd0, bsrc0 + off);
    cp16(dst + bd1, bsrc1 + off);
    if (bok2) cp16(dst + bd2, bsrc2 + off);
  };

  loadA();
  stsA(0);
  loadA();
  issueB(0, 0); CP_COMMIT();
  issueB(1, 1); CP_COMMIT();

  float acc[2][5][4];
#pragma unroll
  for (int m = 0; m < 2; ++m)
#pragma unroll
    for (int n = 0; n < 5; ++n)
#pragma unroll
      for (int v = 0; v < 4; ++v) acc[m][n][v] = 0.0f;

  int bW = 2;
  int bR = 0;
  for (int ch = 0; ch < NCHUNK; ++ch) {
    CP_WAIT1();
    __syncthreads();

    const uint32_t aOff = (uint32_t)((ch & 1) * A_STG_BYTES);
    const uint32_t bOff = (uint32_t)(bR * B_STG_BYTES);
#pragma unroll
    for (int ks = 0; ks < 4; ++ks) {
      uint32_t a0[4], a1[4], b01[4], b23[4], b4[2];
      const uint32_t ko = (uint32_t)(ks * 16 * 2);
      const uint32_t bo = bOff + (uint32_t)(ks * 16 * SB * 2);
      ldsm_x4(a0, aAddr + aOff + ko);
      ldsm_x4(a1, aAddr + aOff + (uint32_t)(16 * SA * 2) + ko);
      ldsm_x4t(b01, bAddrP0 + bo);
      ldsm_x4t(b23, bAddrP1 + bo);
      if (wn == 0) {
        ldsm_x2t(b4, bAddr4 + bo);
        mma_bf16(acc[0][4], a0, b4[0], b4[1]);
        mma_bf16(acc[1][4], a1, b4[0], b4[1]);
      }
      mma_bf16(acc[0][0], a0, b01[0], b01[1]);
      mma_bf16(acc[0][1], a0, b01[2], b01[3]);
      mma_bf16(acc[0][2], a0, b23[0], b23[1]);
      mma_bf16(acc[0][3], a0, b23[2], b23[3]);
      mma_bf16(acc[1][0], a1, b01[0], b01[1]);
      mma_bf16(acc[1][1], a1, b01[2], b01[3]);
      mma_bf16(acc[1][2], a1, b23[0], b23[1]);
      mma_bf16(acc[1][3], a1, b23[2], b23[3]);
    }

    if (ch + 1 < NCHUNK) stsA((ch + 1) & 1);
    if (ch + 2 < NCHUNK) {
      loadA();
      issueB(ch + 2, bW);
      if (++bW == BSTG) bW = 0;
    }
    CP_COMMIT();
    if (++bR == BSTG) bR = 0;
  }

  float* Cp = g_Cp[kh];
  const int ntMax = (wn == 0) ? 5 : 4;
#pragma unroll
  for (int m = 0; m < 2; ++m) {
    const int rr = i0 + wm * 32 + 16 * m + (lane >> 2);
#pragma unroll
    for (int nt = 0; nt < 5; ++nt) {
      if (nt >= ntMax) break;
      const int col = wn * 40 + nt * 8 + 2 * (lane & 3);
      *(float2*)(Cp + (size_t)rr * NC + col) = make_float2(acc[m][nt][0], acc[m][nt][1]);
      *(float2*)(Cp + (size_t)(rr + 8) * NC + col) = make_float2(acc[m][nt][2], acc[m][nt][3]);
    }
  }
}

// ---------------------------------------------------------------------------
// epi_f1: out = feat_row@W1^T + (C0+C1)[:, :64] / (C0[:,64]+C1[:,64]+1)
// 512 blocks x 256 thr, 32 rows/block; W1 j-major in smem (conflict-free).
// ---------------------------------------------------------------------------
__global__ __launch_bounds__(256, 4) void epi_kernel(const float* __restrict__ feat,
                                                     const float* __restrict__ W,
                                                     float* __restrict__ out) {
  extern __shared__ float esm[];
  float* Wt = esm;                 // [64][64]: Wt[j][o] = W1[o][j] = W[o*128 + j]
  float* Fs = esm + 64 * 64;       // [32][65]
  float* inv = esm + 64 * 64 + 32 * 65;   // [32]
  const int tid = threadIdx.x;
  const int r0 = blockIdx.x * 32;

  for (int idx = tid; idx < 64 * 64; idx += 256) {
    int o = idx >> 6, j = idx & 63;
    Wt[j * 64 + o] = W[o * 128 + j];
  }
  for (int idx = tid; idx < 32 * 64; idx += 256) {
    int r = idx >> 6, j = idx & 63;
    Fs[r * 65 + j] = feat[(size_t)(r0 + r) * 64 + j];
  }
  if (tid < 32)
    inv[tid] = 1.0f / (g_Cp[0][(size_t)(r0 + tid) * NC + 64] +
                       g_Cp[1][(size_t)(r0 + tid) * NC + 64] + 1.0f);
  __syncthreads();

  const int r = tid >> 3;          // 0..31
  const int c = (tid & 7) * 8;     // 0,8,...,56
  float acc[8];
#pragma unroll
  for (int v = 0; v < 8; ++v) acc[v] = 0.0f;

#pragma unroll 4
  for (int j = 0; j < 64; ++j) {
    const float f = Fs[r * 65 + j];
    const float4* w4 = (const float4*)(Wt + j * 64 + c);
    const float4 w0 = w4[0];
    const float4 w1 = w4[1];
    acc[0] += f * w0.x; acc[1] += f * w0.y; acc[2] += f * w0.z; acc[3] += f * w0.w;
    acc[4] += f * w1.x; acc[5] += f * w1.y; acc[6] += f * w1.z; acc[7] += f * w1.w;
  }

  const int row = r0 + r;
  const float iv = inv[r];
  const size_t cb = (size_t)row * NC + c;
  const size_t fb = (size_t)row * 64 + c;
#pragma unroll
  for (int h = 0; h < 2; ++h) {
    float4 c0 = *(const float4*)(g_Cp[0] + cb + 4 * h);
    float4 c1 = *(const float4*)(g_Cp[1] + cb + 4 * h);
    *(float4*)(out + fb + 4 * h) =
        make_float4(acc[4 * h + 0] + (c0.x + c1.x) * iv,
                    acc[4 * h + 1] + (c0.y + c1.y) * iv,
                    acc[4 * h + 2] + (c0.z + c1.z) * iv,
                    acc[4 * h + 3] + (c0.w + c1.w) * iv);
  }
}

// ---------------------------------------------------------------------------
extern "C" void kernel_launch(void* const* d_in, const int* in_sizes, int n_in,
                              void* d_out, int out_size) {
  const float* feat = nullptr;
  const float* adj = nullptr;
  const float* W = nullptr;
  for (int i = 0; i < n_in; ++i) {
    if (in_sizes[i] == NROWS * FIN)          feat = (const float*)d_in[i];
    else if (in_sizes[i] == FOUT * 2 * FIN)  W    = (const float*)d_in[i];
    else                                     adj  = (const float*)d_in[i];
  }

  cudaFuncSetAttribute(prepB_kernel, cudaFuncAttributeMaxDynamicSharedMemorySize, PREPB_SMEM);
  cudaFuncSetAttribute(gemm_kernel, cudaFuncAttributeMaxDynamicSharedMemorySize, GEMM_SMEM);
  cudaFuncSetAttribute(epi_kernel, cudaFuncAttributeMaxDynamicSharedMemorySize, EPI_SMEM);

  prepB_kernel<<<NROWS / 64, 256, PREPB_SMEM>>>(feat, W);
  gemm_kernel<<<2 * NBLK, 256, GEMM_SMEM>>>(adj);
  epi_kernel<<<NROWS / 32, 256, EPI_SMEM>>>(feat, W, (float*)d_out);
}

// round 15
// speedup vs baseline: 1.0503x; 1.0503x over previous
#include <cuda_runtime.h>
#include <cuda_bf16.h>
#include <cstdint>

#define NROWS 16384
#define FIN 64
#define FOUT 64
#define NP 80             // g_B row: 0..63 = feat@W2^T, 64 = ones, 65..79 = 0
#define NC 72             // stored C cols
#define MT 128            // M rows per CTA
#define KC 64             // K per chunk
#define KHALF (NROWS / 2)
#define NCHUNK (KHALF / KC)     // 128
#define SA 72             // A smem stride (bf16): conflict-free LDSM
#define SB 88             // B smem stride (bf16): conflict-free LDSM
#define ASTG 2
#define BSTG 3
#define A_STG_BYTES (MT * SA * 2)     // 18432
#define B_STG_BYTES (KC * SB * 2)     // 11264
#define GEMM_SMEM (ASTG * A_STG_BYTES + BSTG * B_STG_BYTES)   // 70656
#define PREP_SMEM ((32 * 65 + 64 * 128) * 4)                  // 41088
#define NBLK (NROWS / MT)       // 128 row blocks

__device__ __align__(256) __nv_bfloat16 g_B[NROWS * NP];
__device__ __align__(256) float g_F1[NROWS * FOUT];
__device__ __align__(256) float g_Cp[2][NROWS * NC];

__device__ __forceinline__ uint32_t smem_u32(const void* p) {
  uint32_t a;
  asm("{ .reg .u64 t; cvta.to.shared.u64 t, %1; cvt.u32.u64 %0, t; }" : "=r"(a) : "l"(p));
  return a;
}
__device__ __forceinline__ void cp16(uint32_t dst, const void* src) {
  asm volatile("cp.async.cg.shared.global [%0], [%1], 16;" :: "r"(dst), "l"(src));
}
#define CP_COMMIT() asm volatile("cp.async.commit_group;" ::: "memory")
#define CP_WAIT1()  asm volatile("cp.async.wait_group 1;" ::: "memory")
__device__ __forceinline__ void ldsm_x4(uint32_t* r, uint32_t a) {
  asm volatile("ldmatrix.sync.aligned.m8n8.x4.shared.b16 {%0,%1,%2,%3}, [%4];"
               : "=r"(r[0]), "=r"(r[1]), "=r"(r[2]), "=r"(r[3]) : "r"(a));
}
__device__ __forceinline__ void ldsm_x4t(uint32_t* r, uint32_t a) {
  asm volatile("ldmatrix.sync.aligned.m8n8.x4.trans.shared.b16 {%0,%1,%2,%3}, [%4];"
               : "=r"(r[0]), "=r"(r[1]), "=r"(r[2]), "=r"(r[3]) : "r"(a));
}
__device__ __forceinline__ void ldsm_x2t(uint32_t* r, uint32_t a) {
  asm volatile("ldmatrix.sync.aligned.m8n8.x2.trans.shared.b16 {%0,%1}, [%2];"
               : "=r"(r[0]), "=r"(r[1]) : "r"(a));
}
__device__ __forceinline__ void mma_bf16(float* c, const uint32_t* a, uint32_t b0, uint32_t b1) {
  asm volatile(
      "mma.sync.aligned.m16n8k16.row.col.f32.bf16.bf16.f32 "
      "{%0,%1,%2,%3}, {%4,%5,%6,%7}, {%8,%9}, {%0,%1,%2,%3};\n"
      : "+f"(c[0]), "+f"(c[1]), "+f"(c[2]), "+f"(c[3])
      : "r"(a[0]), "r"(a[1]), "r"(a[2]), "r"(a[3]), "r"(b0), "r"(b1));
}

// ---------------------------------------------------------------------------
// prep: g_F1 = feat@W1^T (fp32); g_B = feat@W2^T (bf16) | ones | 0-pad.
// 512 CTAs x 256 thr x occ4: 32 rows/CTA, q = warp 0..7 -> 16 cols each.
// Weight reads are warp-broadcast LDS.128; Fs reads conflict-free.
// ---------------------------------------------------------------------------
__global__ __launch_bounds__(256, 4) void prep_kernel(const float* __restrict__ feat,
                                                      const float* __restrict__ W) {
  extern __shared__ float sm[];
  float* Fs = sm;             // [32][65]
  float* Wt = sm + 32 * 65;   // [64][128]: Wt[j][o]=W1[o][j], Wt[j][64+o]=W2[o][j]
  const int tid = threadIdx.x;
  const int k0 = blockIdx.x * 32;

  for (int idx = tid; idx < 32 * 64; idx += 256) {
    int r = idx >> 6, j = idx & 63;
    Fs[r * 65 + j] = feat[(size_t)(k0 + r) * 64 + j];
  }
  for (int idx = tid; idx < 64 * 128; idx += 256) {
    int o = idx >> 7, j = idx & 127;
    Wt[(j & 63) * 128 + ((j < 64) ? o : 64 + o)] = W[idx];
  }
  __syncthreads();

  const int r = tid & 31;
  const int q = tid >> 5;     // warp id 0..7, warp-uniform
  float acc[16];
#pragma unroll
  for (int o = 0; o < 16; ++o) acc[o] = 0.0f;

#pragma unroll 4
  for (int j = 0; j < 64; ++j) {
    const float f = Fs[r * 65 + j];
    const float4* w4 = (const float4*)(Wt + j * 128 + q * 16);  // warp-broadcast
#pragma unroll
    for (int v = 0; v < 4; ++v) {
      const float4 w = w4[v];
      acc[4 * v + 0] += f * w.x;
      acc[4 * v + 1] += f * w.y;
      acc[4 * v + 2] += f * w.z;
      acc[4 * v + 3] += f * w.w;
    }
  }

  if (q < 4) {
    float4* dst = (float4*)(g_F1 + (size_t)(k0 + r) * 64 + q * 16);
#pragma unroll
    for (int v = 0; v < 4; ++v)
      dst[v] = make_float4(acc[4 * v], acc[4 * v + 1], acc[4 * v + 2], acc[4 * v + 3]);
  } else {
    __nv_bfloat162* dst = (__nv_bfloat162*)(g_B + (size_t)(k0 + r) * NP + (q - 4) * 16);
#pragma unroll
    for (int v = 0; v < 8; ++v)
      dst[v] = __floats2bfloat162_rn(acc[2 * v], acc[2 * v + 1]);
  }
  for (int idx = tid; idx < 32 * 16; idx += 256) {
    int rr = idx >> 4, c = 64 + (idx & 15);
    g_B[(size_t)(k0 + rr) * NP + c] = __float2bfloat16((c == 64) ? 1.0f : 0.0f);
  }
}

// ---------------------------------------------------------------------------
// gemm (r8/r12 structure, exact): Cp[kh][rowBlk] = adj(rows, k-half) @ g_B
// ---------------------------------------------------------------------------
__global__ __launch_bounds__(256, 2) void gemm_kernel(const float* __restrict__ adj) {
  extern __shared__ __align__(128) char smem[];
  __nv_bfloat16* As = (__nv_bfloat16*)smem;
  __nv_bfloat16* Bs = (__nv_bfloat16*)(smem + ASTG * A_STG_BYTES);

  const int tid = threadIdx.x;
  const int warp = tid >> 5;
  const int lane = tid & 31;
  const int wm = warp >> 1;
  const int wn = warp & 1;
  const int rowBlk = blockIdx.x >> 1;
  const int kh = blockIdx.x & 1;
  const int i0 = rowBlk * MT;
  const size_t kbase0 = (size_t)kh * KHALF;

  const int r0 = tid >> 4;
  const int c4 = tid & 15;
  const float* apc = adj + (size_t)(i0 + r0) * NROWS + kbase0 + c4 * 4;
  const uint32_t a_base = smem_u32(As);
  const uint32_t aSt0 = a_base + (uint32_t)(r0 * SA + c4 * 4) * 2;

  const int br0 = tid / 10, bc0 = tid % 10;
  const int br1 = (tid + 256) / 10, bc1 = (tid + 256) % 10;
  const int br2 = (tid + 512) / 10, bc2 = (tid + 512) % 10;
  const bool bok2 = tid < 128;
  const uint32_t bs_base = smem_u32(Bs);
  const __nv_bfloat16* bsrc0 = g_B + (kbase0 + br0) * NP + bc0 * 8;
  const __nv_bfloat16* bsrc1 = g_B + (kbase0 + br1) * NP + bc1 * 8;
  const __nv_bfloat16* bsrc2 = g_B + (kbase0 + br2) * NP + bc2 * 8;
  const uint32_t bd0 = (uint32_t)(br0 * SB * 2 + bc0 * 16);
  const uint32_t bd1 = (uint32_t)(br1 * SB * 2 + bc1 * 16);
  const uint32_t bd2 = (uint32_t)(br2 * SB * 2 + bc2 * 16);

  const uint32_t aAddr = a_base +
      (uint32_t)((wm * 32 + (lane & 15)) * SA + (lane >> 4) * 8) * 2;
  const int bRow = lane & 15;
  const int nOff = (lane >> 4) * 8;
  const uint32_t bAddrP0 = bs_base + (uint32_t)(bRow * SB + wn * 40 + nOff) * 2;
  const uint32_t bAddrP1 = bAddrP0 + 16 * 2;
  const uint32_t bAddr4 = bs_base + (uint32_t)(bRow * SB + 32 + nOff) * 2;

  float4 rA[8];
  auto loadA = [&]() {
#pragma unroll
    for (int j = 0; j < 8; ++j) {
      asm volatile("ld.global.nc.L2::128B.v4.f32 {%0,%1,%2,%3}, [%4];"
                   : "=f"(rA[j].x), "=f"(rA[j].y), "=f"(rA[j].z), "=f"(rA[j].w)
                   : "l"(apc + (size_t)j * 16 * NROWS));
    }
    apc += KC;
  };
  auto stsA = [&](int stg) {
    const uint32_t base = aSt0 + (uint32_t)(stg * A_STG_BYTES);
#pragma unroll
    for (int j = 0; j < 8; ++j) {
      __nv_bfloat162 lo = __floats2bfloat162_rn(rA[j].x, rA[j].y);
      __nv_bfloat162 hi = __floats2bfloat162_rn(rA[j].z, rA[j].w);
      asm volatile("st.shared.v2.b32 [%0], {%1,%2};"
                   :: "r"(base + (uint32_t)(j * 16 * SA * 2)),
                      "r"(*(uint32_t*)&lo), "r"(*(uint32_t*)&hi)
                   : "memory");
    }
  };
  auto issueB = [&](int ch, int stg) {
    const uint32_t dst = bs_base + (uint32_t)(stg * B_STG_BYTES);
    const size_t off = (size_t)ch * KC * NP;
    cp16(dst + bd0, bsrc0 + off);
    cp16(dst + bd1, bsrc1 + off);
    if (bok2) cp16(dst + bd2, bsrc2 + off);
  };

  loadA();
  stsA(0);
  loadA();
  issueB(0, 0); CP_COMMIT();
  issueB(1, 1); CP_COMMIT();

  float acc[2][5][4];
#pragma unroll
  for (int m = 0; m < 2; ++m)
#pragma unroll
    for (int n = 0; n < 5; ++n)
#pragma unroll
      for (int v = 0; v < 4; ++v) acc[m][n][v] = 0.0f;

  int bW = 2;
  int bR = 0;
  for (int ch = 0; ch < NCHUNK; ++ch) {
    CP_WAIT1();
    __syncthreads();

    const uint32_t aOff = (uint32_t)((ch & 1) * A_STG_BYTES);
    const uint32_t bOff = (uint32_t)(bR * B_STG_BYTES);
#pragma unroll
    for (int ks = 0; ks < 4; ++ks) {
      uint32_t a0[4], a1[4], b01[4], b23[4], b4[2];
      const uint32_t ko = (uint32_t)(ks * 16 * 2);
      const uint32_t bo = bOff + (uint32_t)(ks * 16 * SB * 2);
      ldsm_x4(a0, aAddr + aOff + ko);
      ldsm_x4(a1, aAddr + aOff + (uint32_t)(16 * SA * 2) + ko);
      ldsm_x4t(b01, bAddrP0 + bo);
      ldsm_x4t(b23, bAddrP1 + bo);
      if (wn == 0) {
        ldsm_x2t(b4, bAddr4 + bo);
        mma_bf16(acc[0][4], a0, b4[0], b4[1]);
        mma_bf16(acc[1][4], a1, b4[0], b4[1]);
      }
      mma_bf16(acc[0][0], a0, b01[0], b01[1]);
      mma_bf16(acc[0][1], a0, b01[2], b01[3]);
      mma_bf16(acc[0][2], a0, b23[0], b23[1]);
      mma_bf16(acc[0][3], a0, b23[2], b23[3]);
      mma_bf16(acc[1][0], a1, b01[0], b01[1]);
      mma_bf16(acc[1][1], a1, b01[2], b01[3]);
      mma_bf16(acc[1][2], a1, b23[0], b23[1]);
      mma_bf16(acc[1][3], a1, b23[2], b23[3]);
    }

    if (ch + 1 < NCHUNK) stsA((ch + 1) & 1);
    if (ch + 2 < NCHUNK) {
      loadA();
      issueB(ch + 2, bW);
      if (++bW == BSTG) bW = 0;
    }
    CP_COMMIT();
    if (++bR == BSTG) bR = 0;
  }

  float* Cp = g_Cp[kh];
  const int ntMax = (wn == 0) ? 5 : 4;
#pragma unroll
  for (int m = 0; m < 2; ++m) {
    const int rr = i0 + wm * 32 + 16 * m + (lane >> 2);
#pragma unroll
    for (int nt = 0; nt < 5; ++nt) {
      if (nt >= ntMax) break;
      const int col = wn * 40 + nt * 8 + 2 * (lane & 3);
      *(float2*)(Cp + (size_t)rr * NC + col) = make_float2(acc[m][nt][0], acc[m][nt][1]);
      *(float2*)(Cp + (size_t)(rr + 8) * NC + col) = make_float2(acc[m][nt][2], acc[m][nt][3]);
    }
  }
}

// ---------------------------------------------------------------------------
// epi: out = F1 + (C0 + C1)[:, :64] / (C0[:,64] + C1[:,64] + 1)
// ---------------------------------------------------------------------------
__global__ __launch_bounds__(256, 8) void epi_kernel(float* __restrict__ out) {
  __shared__ float inv[32];
  const int tid = threadIdx.x;
  const int r0 = blockIdx.x * 32;

  if (tid < 32)
    inv[tid] = 1.0f / (g_Cp[0][(size_t)(r0 + tid) * NC + 64] +
                       g_Cp[1][(size_t)(r0 + tid) * NC + 64] + 1.0f);
  __syncthreads();

  const int r = tid >> 3;
  const int c = (tid & 7) * 8;
  const int row = r0 + r;
  const float iv = inv[r];
  const size_t cb = (size_t)row * NC + c;
  const size_t fb = (size_t)row * 64 + c;
#pragma unroll
  for (int h = 0; h < 2; ++h) {
    float4 c0 = *(const float4*)(g_Cp[0] + cb + 4 * h);
    float4 c1 = *(const float4*)(g_Cp[1] + cb + 4 * h);
    float4 f = *(const float4*)(g_F1 + fb + 4 * h);
    *(float4*)(out + fb + 4 * h) =
        make_float4(f.x + (c0.x + c1.x) * iv, f.y + (c0.y + c1.y) * iv,
                    f.z + (c0.z + c1.z) * iv, f.w + (c0.w + c1.w) * iv);
  }
}

// ---------------------------------------------------------------------------
extern "C" void kernel_launch(void* const* d_in, const int* in_sizes, int n_in,
                              void* d_out, int out_size) {
  const float* feat = nullptr;
  const float* adj = nullptr;
  const float* W = nullptr;
  for (int i = 0; i < n_in; ++i) {
    if (in_sizes[i] == NROWS * FIN)          feat = (const float*)d_in[i];
    else if (in_sizes[i] == FOUT * 2 * FIN)  W    = (const float*)d_in[i];
    else                                     adj  = (const float*)d_in[i];
  }

  cudaFuncSetAttribute(prep_kernel, cudaFuncAttributeMaxDynamicSharedMemorySize, PREP_SMEM);
  cudaFuncSetAttribute(gemm_kernel, cudaFuncAttributeMaxDynamicSharedMemorySize, GEMM_SMEM);

  prep_kernel<<<NROWS / 32, 256, PREP_SMEM>>>(feat, W);
  gemm_kernel<<<2 * NBLK, 256, GEMM_SMEM>>>(adj);
  epi_kernel<<<NROWS / 32, 256>>>((float*)d_out);
}

// round 16
// speedup vs baseline: 1.1009x; 1.0481x over previous
#include <cuda_runtime.h>
#include <cuda_bf16.h>
#include <cstdint>

#define NROWS 16384
#define FIN 64
#define FOUT 64
#define NP 80             // g_B row: 0..63 = feat@W2^T, 64 = ones, 65..79 = 0
#define NC 72             // stored C cols
#define MT 128            // M rows per CTA
#define KC 64             // K per chunk
#define KHALF (NROWS / 2)
#define NCHUNK (KHALF / KC)     // 128
#define SA 72             // A smem stride (bf16): conflict-free LDSM
#define SB 88             // B smem stride (bf16): conflict-free LDSM
#define ASTG 2
#define BSTG 3
#define A_STG_BYTES (MT * SA * 2)     // 18432
#define B_STG_BYTES (KC * SB * 2)     // 11264
#define GEMM_SMEM (ASTG * A_STG_BYTES + BSTG * B_STG_BYTES)   // 70656
#define WTS 132           // Wt stride (words): 4-way fill conflict, 16B-aligned reads
#define PREP_SMEM ((64 * 65 + 64 * WTS) * 4)                  // 50432
#define NBLK (NROWS / MT)       // 128 row blocks

__device__ __align__(256) __nv_bfloat16 g_B[NROWS * NP];
__device__ __align__(256) float g_F1[NROWS * FOUT];
__device__ __align__(256) float g_Cp[2][NROWS * NC];

__device__ __forceinline__ uint32_t smem_u32(const void* p) {
  uint32_t a;
  asm("{ .reg .u64 t; cvta.to.shared.u64 t, %1; cvt.u32.u64 %0, t; }" : "=r"(a) : "l"(p));
  return a;
}
__device__ __forceinline__ void cp16(uint32_t dst, const void* src) {
  asm volatile("cp.async.cg.shared.global [%0], [%1], 16;" :: "r"(dst), "l"(src));
}
#define CP_COMMIT() asm volatile("cp.async.commit_group;" ::: "memory")
#define CP_WAIT1()  asm volatile("cp.async.wait_group 1;" ::: "memory")
__device__ __forceinline__ void ldsm_x4(uint32_t* r, uint32_t a) {
  asm volatile("ldmatrix.sync.aligned.m8n8.x4.shared.b16 {%0,%1,%2,%3}, [%4];"
               : "=r"(r[0]), "=r"(r[1]), "=r"(r[2]), "=r"(r[3]) : "r"(a));
}
__device__ __forceinline__ void ldsm_x4t(uint32_t* r, uint32_t a) {
  asm volatile("ldmatrix.sync.aligned.m8n8.x4.trans.shared.b16 {%0,%1,%2,%3}, [%4];"
               : "=r"(r[0]), "=r"(r[1]), "=r"(r[2]), "=r"(r[3]) : "r"(a));
}
__device__ __forceinline__ void ldsm_x2t(uint32_t* r, uint32_t a) {
  asm volatile("ldmatrix.sync.aligned.m8n8.x2.trans.shared.b16 {%0,%1}, [%2];"
               : "=r"(r[0]), "=r"(r[1]) : "r"(a));
}
__device__ __forceinline__ void mma_bf16(float* c, const uint32_t* a, uint32_t b0, uint32_t b1) {
  asm volatile(
      "mma.sync.aligned.m16n8k16.row.col.f32.bf16.bf16.f32 "
      "{%0,%1,%2,%3}, {%4,%5,%6,%7}, {%8,%9}, {%0,%1,%2,%3};\n"
      : "+f"(c[0]), "+f"(c[1]), "+f"(c[2]), "+f"(c[3])
      : "r"(a[0]), "r"(a[1]), "r"(a[2]), "r"(a[3]), "r"(b0), "r"(b1));
}

// ---------------------------------------------------------------------------
// prep (r13 + conflict-fixed fill): 512 thr, 16 outputs/thread.
// g_F1 = feat@W1^T (fp32); g_B = feat@W2^T (bf16) | ones | 0-pad.
// Wt stride 132: fill conflict 32-way -> 4-way; reads stay 16B-aligned bcast.
// ---------------------------------------------------------------------------
__global__ __launch_bounds__(512, 2) void prep_kernel(const float* __restrict__ feat,
                                                      const float* __restrict__ W) {
  extern __shared__ float sm[];
  float* Fs = sm;             // [64][65]
  float* Wt = sm + 64 * 65;   // [64][WTS]: Wt[j][o]=W1[o][j], Wt[j][64+o]=W2[o][j]
  const int tid = threadIdx.x;
  const int k0 = blockIdx.x * 64;

  for (int idx = tid; idx < 64 * 64; idx += 512) {
    int r = idx >> 6, j = idx & 63;
    Fs[r * 65 + j] = feat[(size_t)(k0 + r) * 64 + j];
  }
  for (int idx = tid; idx < 64 * 128; idx += 512) {
    int o = idx >> 7, j = idx & 127;
    Wt[(j & 63) * WTS + ((j < 64) ? o : 64 + o)] = W[idx];
  }
  __syncthreads();

  const int r = tid & 63;
  const int q = tid >> 6;     // 0..7, warp-uniform
  float acc[16];
#pragma unroll
  for (int o = 0; o < 16; ++o) acc[o] = 0.0f;

#pragma unroll 4
  for (int j = 0; j < 64; ++j) {
    const float f = Fs[r * 65 + j];
    const float4* w4 = (const float4*)(Wt + j * WTS + q * 16);  // warp-broadcast
#pragma unroll
    for (int v = 0; v < 4; ++v) {
      const float4 w = w4[v];
      acc[4 * v + 0] += f * w.x;
      acc[4 * v + 1] += f * w.y;
      acc[4 * v + 2] += f * w.z;
      acc[4 * v + 3] += f * w.w;
    }
  }

  if (q < 4) {
    float4* dst = (float4*)(g_F1 + (size_t)(k0 + r) * 64 + q * 16);
#pragma unroll
    for (int v = 0; v < 4; ++v)
      dst[v] = make_float4(acc[4 * v], acc[4 * v + 1], acc[4 * v + 2], acc[4 * v + 3]);
  } else {
    __nv_bfloat162* dst = (__nv_bfloat162*)(g_B + (size_t)(k0 + r) * NP + (q - 4) * 16);
#pragma unroll
    for (int v = 0; v < 8; ++v)
      dst[v] = __floats2bfloat162_rn(acc[2 * v], acc[2 * v + 1]);
  }
  for (int idx = tid; idx < 64 * 16; idx += 512) {
    int rr = idx >> 4, c = 64 + (idx & 15);
    g_B[(size_t)(k0 + rr) * NP + c] = __float2bfloat16((c == 64) ? 1.0f : 0.0f);
  }
}

// ---------------------------------------------------------------------------
// gemm (r8/r12 structure, exact): Cp[kh][rowBlk] = adj(rows, k-half) @ g_B
// ---------------------------------------------------------------------------
__global__ __launch_bounds__(256, 2) void gemm_kernel(const float* __restrict__ adj) {
  extern __shared__ __align__(128) char smem[];
  __nv_bfloat16* As = (__nv_bfloat16*)smem;
  __nv_bfloat16* Bs = (__nv_bfloat16*)(smem + ASTG * A_STG_BYTES);

  const int tid = threadIdx.x;
  const int warp = tid >> 5;
  const int lane = tid & 31;
  const int wm = warp >> 1;
  const int wn = warp & 1;
  const int rowBlk = blockIdx.x >> 1;
  const int kh = blockIdx.x & 1;
  const int i0 = rowBlk * MT;
  const size_t kbase0 = (size_t)kh * KHALF;

  const int r0 = tid >> 4;
  const int c4 = tid & 15;
  const float* apc = adj + (size_t)(i0 + r0) * NROWS + kbase0 + c4 * 4;
  const uint32_t a_base = smem_u32(As);
  const uint32_t aSt0 = a_base + (uint32_t)(r0 * SA + c4 * 4) * 2;

  const int br0 = tid / 10, bc0 = tid % 10;
  const int br1 = (tid + 256) / 10, bc1 = (tid + 256) % 10;
  const int br2 = (tid + 512) / 10, bc2 = (tid + 512) % 10;
  const bool bok2 = tid < 128;
  const uint32_t bs_base = smem_u32(Bs);
  const __nv_bfloat16* bsrc0 = g_B + (kbase0 + br0) * NP + bc0 * 8;
  const __nv_bfloat16* bsrc1 = g_B + (kbase0 + br1) * NP + bc1 * 8;
  const __nv_bfloat16* bsrc2 = g_B + (kbase0 + br2) * NP + bc2 * 8;
  const uint32_t bd0 = (uint32_t)(br0 * SB * 2 + bc0 * 16);
  const uint32_t bd1 = (uint32_t)(br1 * SB * 2 + bc1 * 16);
  const uint32_t bd2 = (uint32_t)(br2 * SB * 2 + bc2 * 16);

  const uint32_t aAddr = a_base +
      (uint32_t)((wm * 32 + (lane & 15)) * SA + (lane >> 4) * 8) * 2;
  const int bRow = lane & 15;
  const int nOff = (lane >> 4) * 8;
  const uint32_t bAddrP0 = bs_base + (uint32_t)(bRow * SB + wn * 40 + nOff) * 2;
  const uint32_t bAddrP1 = bAddrP0 + 16 * 2;
  const uint32_t bAddr4 = bs_base + (uint32_t)(bRow * SB + 32 + nOff) * 2;

  float4 rA[8];
  auto loadA = [&]() {
#pragma unroll
    for (int j = 0; j < 8; ++j) {
      asm volatile("ld.global.nc.L2::128B.v4.f32 {%0,%1,%2,%3}, [%4];"
                   : "=f"(rA[j].x), "=f"(rA[j].y), "=f"(rA[j].z), "=f"(rA[j].w)
                   : "l"(apc + (size_t)j * 16 * NROWS));
    }
    apc += KC;
  };
  auto stsA = [&](int stg) {
    const uint32_t base = aSt0 + (uint32_t)(stg * A_STG_BYTES);
#pragma unroll
    for (int j = 0; j < 8; ++j) {
      __nv_bfloat162 lo = __floats2bfloat162_rn(rA[j].x, rA[j].y);
      __nv_bfloat162 hi = __floats2bfloat162_rn(rA[j].z, rA[j].w);
      asm volatile("st.shared.v2.b32 [%0], {%1,%2};"
                   :: "r"(base + (uint32_t)(j * 16 * SA * 2)),
                      "r"(*(uint32_t*)&lo), "r"(*(uint32_t*)&hi)
                   : "memory");
    }
  };
  auto issueB = [&](int ch, int stg) {
    const uint32_t dst = bs_base + (uint32_t)(stg * B_STG_BYTES);
    const size_t off = (size_t)ch * KC * NP;
    cp16(dst + bd0, bsrc0 + off);
    cp16(dst + bd1, bsrc1 + off);
    if (bok2) cp16(dst + bd2, bsrc2 + off);
  };

  loadA();
  stsA(0);
  loadA();
  issueB(0, 0); CP_COMMIT();
  issueB(1, 1); CP_COMMIT();

  float acc[2][5][4];
#pragma unroll
  for (int m = 0; m < 2; ++m)
#pragma unroll
    for (int n = 0; n < 5; ++n)
#pragma unroll
      for (int v = 0; v < 4; ++v) acc[m][n][v] = 0.0f;

  int bW = 2;
  int bR = 0;
  for (int ch = 0; ch < NCHUNK; ++ch) {
    CP_WAIT1();
    __syncthreads();

    const uint32_t aOff = (uint32_t)((ch & 1) * A_STG_BYTES);
    const uint32_t bOff = (uint32_t)(bR * B_STG_BYTES);
#pragma unroll
    for (int ks = 0; ks < 4; ++ks) {
      uint32_t a0[4], a1[4], b01[4], b23[4], b4[2];
      const uint32_t ko = (uint32_t)(ks * 16 * 2);
      const uint32_t bo = bOff + (uint32_t)(ks * 16 * SB * 2);
      ldsm_x4(a0, aAddr + aOff + ko);
      ldsm_x4(a1, aAddr + aOff + (uint32_t)(16 * SA * 2) + ko);
      ldsm_x4t(b01, bAddrP0 + bo);
      ldsm_x4t(b23, bAddrP1 + bo);
      if (wn == 0) {
        ldsm_x2t(b4, bAddr4 + bo);
        mma_bf16(acc[0][4], a0, b4[0], b4[1]);
        mma_bf16(acc[1][4], a1, b4[0], b4[1]);
      }
      mma_bf16(acc[0][0], a0, b01[0], b01[1]);
      mma_bf16(acc[0][1], a0, b01[2], b01[3]);
      mma_bf16(acc[0][2], a0, b23[0], b23[1]);
      mma_bf16(acc[0][3], a0, b23[2], b23[3]);
      mma_bf16(acc[1][0], a1, b01[0], b01[1]);
      mma_bf16(acc[1][1], a1, b01[2], b01[3]);
      mma_bf16(acc[1][2], a1, b23[0], b23[1]);
      mma_bf16(acc[1][3], a1, b23[2], b23[3]);
    }

    if (ch + 1 < NCHUNK) stsA((ch + 1) & 1);
    if (ch + 2 < NCHUNK) {
      loadA();
      issueB(ch + 2, bW);
      if (++bW == BSTG) bW = 0;
    }
    CP_COMMIT();
    if (++bR == BSTG) bR = 0;
  }

  float* Cp = g_Cp[kh];
  const int ntMax = (wn == 0) ? 5 : 4;
#pragma unroll
  for (int m = 0; m < 2; ++m) {
    const int rr = i0 + wm * 32 + 16 * m + (lane >> 2);
#pragma unroll
    for (int nt = 0; nt < 5; ++nt) {
      if (nt >= ntMax) break;
      const int col = wn * 40 + nt * 8 + 2 * (lane & 3);
      *(float2*)(Cp + (size_t)rr * NC + col) = make_float2(acc[m][nt][0], acc[m][nt][1]);
      *(float2*)(Cp + (size_t)(rr + 8) * NC + col) = make_float2(acc[m][nt][2], acc[m][nt][3]);
    }
  }
}

// ---------------------------------------------------------------------------
// epi: out = F1 + (C0 + C1)[:, :64] / (C0[:,64] + C1[:,64] + 1)
// ---------------------------------------------------------------------------
__global__ __launch_bounds__(256, 8) void epi_kernel(float* __restrict__ out) {
  __shared__ float inv[32];
  const int tid = threadIdx.x;
  const int r0 = blockIdx.x * 32;

  if (tid < 32)
    inv[tid] = 1.0f / (g_Cp[0][(size_t)(r0 + tid) * NC + 64] +
                       g_Cp[1][(size_t)(r0 + tid) * NC + 64] + 1.0f);
  __syncthreads();

  const int r = tid >> 3;
  const int c = (tid & 7) * 8;
  const int row = r0 + r;
  const float iv = inv[r];
  const size_t cb = (size_t)row * NC + c;
  const size_t fb = (size_t)row * 64 + c;
#pragma unroll
  for (int h = 0; h < 2; ++h) {
    float4 c0 = *(const float4*)(g_Cp[0] + cb + 4 * h);
    float4 c1 = *(const float4*)(g_Cp[1] + cb + 4 * h);
    float4 f = *(const float4*)(g_F1 + fb + 4 * h);
    *(float4*)(out + fb + 4 * h) =
        make_float4(f.x + (c0.x + c1.x) * iv, f.y + (c0.y + c1.y) * iv,
                    f.z + (c0.z + c1.z) * iv, f.w + (c0.w + c1.w) * iv);
  }
}

// ---------------------------------------------------------------------------
extern "C" void kernel_launch(void* const* d_in, const int* in_sizes, int n_in,
                              void* d_out, int out_size) {
  const float* feat = nullptr;
  const float* adj = nullptr;
  const float* W = nullptr;
  for (int i = 0; i < n_in; ++i) {
    if (in_sizes[i] == NROWS * FIN)          feat = (const float*)d_in[i];
    else if (in_sizes[i] == FOUT * 2 * FIN)  W    = (const float*)d_in[i];
    else                                     adj  = (const float*)d_in[i];
  }

  cudaFuncSetAttribute(prep_kernel, cudaFuncAttributeMaxDynamicSharedMemorySize, PREP_SMEM);
  cudaFuncSetAttribute(gemm_kernel, cudaFuncAttributeMaxDynamicSharedMemorySize, GEMM_SMEM);

  prep_kernel<<<NROWS / 64, 512, PREP_SMEM>>>(feat, W);
  gemm_kernel<<<2 * NBLK, 256, GEMM_SMEM>>>(adj);
  epi_kernel<<<NROWS / 32, 256>>>((float*)d_out);
}